// round 1
// baseline (speedup 1.0000x reference)
#include <cuda_runtime.h>
#include <cstdint>
#include <cstddef>

#define SLEN 2048
#define HD 64
#define NBH 64
#define TQ 128
#define TK 128
#define PAD 68    // Q/K/V smem row pad (floats) -> conflict-free frag loads
#define PADP 132  // P smem row pad
#define NTHREADS 256

// smem layout (floats):
// loop1: qs[128*68]=8704 | ks[128*68]=8704                (17408)
// loop2: ps[128*132]=16896 | vs[128*68]=8704              (25600)
// stats: ms[128], ls[128] at 25600                         (25856 total floats)
#define SMEM_FLOATS (TQ*PADP + TK*PAD + 2*TQ)
#define SMEM_BYTES (SMEM_FLOATS * 4)

__device__ __forceinline__ uint32_t f2tf32(float f) {
    uint32_t u;
    asm("cvt.rna.tf32.f32 %0, %1;\n" : "=r"(u) : "f"(f));
    return u;
}

__device__ __forceinline__ void mma_tf32(float c[4],
    uint32_t a0, uint32_t a1, uint32_t a2, uint32_t a3,
    uint32_t b0, uint32_t b1)
{
    asm volatile(
        "mma.sync.aligned.m16n8k8.row.col.f32.tf32.tf32.f32 "
        "{%0,%1,%2,%3}, {%4,%5,%6,%7}, {%8,%9}, {%0,%1,%2,%3};\n"
        : "+f"(c[0]), "+f"(c[1]), "+f"(c[2]), "+f"(c[3])
        : "r"(a0), "r"(a1), "r"(a2), "r"(a3), "r"(b0), "r"(b1));
}

__global__ __launch_bounds__(NTHREADS, 1)
void sdpa_kernel(const float* __restrict__ q, const float* __restrict__ k,
                 const float* __restrict__ v, float* __restrict__ out,
                 float* __restrict__ attn)
{
    extern __shared__ float smem[];
    float* qs = smem;                       // [128][68]
    float* ks = smem + TQ * PAD;            // [128][68]
    float* ps = smem;                       // [128][132] (reuses qs/ks in phase 2)
    float* vs = smem + TQ * PADP;           // [128][68]
    float* ms = smem + TQ * PADP + TK * PAD;  // [128]
    float* ls = ms + TQ;                    // [128]

    const int qt = blockIdx.x;
    const int bh = blockIdx.y;
    const int q0 = qt * TQ;
    const int tid = threadIdx.x;
    const int lane = tid & 31;
    const int warp = tid >> 5;
    const int g = lane >> 2;    // 0..7
    const int qd = lane & 3;    // 0..3
    const int row0 = warp * 16; // warp owns 16 query rows

    const float* qg = q + (size_t)bh * SLEN * HD;
    const float* kg = k + (size_t)bh * SLEN * HD;
    const float* vg = v + (size_t)bh * SLEN * HD;
    float* og = out + (size_t)bh * SLEN * HD;
    float* ag = attn + (size_t)bh * SLEN * SLEN;

    // ---- load Q tile (pre-scaled by 1/temperature), tf32-rounded ----
    {
        const float4* qg4 = (const float4*)(qg + (size_t)q0 * HD);
        #pragma unroll
        for (int i = 0; i < 8; i++) {
            int vv = tid + i * NTHREADS;        // 2048 float4s = 128x64
            int r = vv >> 4, c4 = vv & 15;
            float4 t = qg4[vv];
            uint32_t* dst = (uint32_t*)&qs[r * PAD + c4 * 4];
            dst[0] = f2tf32(t.x * 0.125f);
            dst[1] = f2tf32(t.y * 0.125f);
            dst[2] = f2tf32(t.z * 0.125f);
            dst[3] = f2tf32(t.w * 0.125f);
        }
    }

    // ---- phase 1: S = Q K^T (tf32 mma), write raw scores, online m/l ----
    float m0 = -1e30f, m8 = -1e30f, l0 = 0.f, l8 = 0.f;

    for (int kt = 0; kt < SLEN / TK; kt++) {
        __syncthreads();  // previous iteration's reads of ks done
        const float4* kg4 = (const float4*)(kg + (size_t)kt * TK * HD);
        #pragma unroll
        for (int i = 0; i < 8; i++) {
            int vv = tid + i * NTHREADS;
            int r = vv >> 4, c4 = vv & 15;
            float4 t = kg4[vv];
            uint32_t* dst = (uint32_t*)&ks[r * PAD + c4 * 4];
            dst[0] = f2tf32(t.x); dst[1] = f2tf32(t.y);
            dst[2] = f2tf32(t.z); dst[3] = f2tf32(t.w);
        }
        __syncthreads();

        float c[16][4];
        #pragma unroll
        for (int n = 0; n < 16; n++) { c[n][0]=0.f; c[n][1]=0.f; c[n][2]=0.f; c[n][3]=0.f; }

        const uint32_t* qsu = (const uint32_t*)qs;
        const uint32_t* ksu = (const uint32_t*)ks;
        #pragma unroll
        for (int kk = 0; kk < 8; kk++) {
            uint32_t a0 = qsu[(row0 + g)     * PAD + kk * 8 + qd];
            uint32_t a1 = qsu[(row0 + g + 8) * PAD + kk * 8 + qd];
            uint32_t a2 = qsu[(row0 + g)     * PAD + kk * 8 + qd + 4];
            uint32_t a3 = qsu[(row0 + g + 8) * PAD + kk * 8 + qd + 4];
            #pragma unroll
            for (int n = 0; n < 16; n++) {
                uint32_t b0 = ksu[(n * 8 + g) * PAD + kk * 8 + qd];
                uint32_t b1 = ksu[(n * 8 + g) * PAD + kk * 8 + qd + 4];
                mma_tf32(c[n], a0, a1, a2, a3, b0, b1);
            }
        }

        // store raw scores to the attn region (scratch)
        float* arow0 = ag + (size_t)(q0 + row0 + g) * SLEN + kt * TK;
        float* arow8 = arow0 + (size_t)8 * SLEN;
        #pragma unroll
        for (int n = 0; n < 16; n++) {
            int col = n * 8 + qd * 2;
            *(float2*)(arow0 + col) = make_float2(c[n][0], c[n][1]);
            *(float2*)(arow8 + col) = make_float2(c[n][2], c[n][3]);
        }

        // online softmax stats (rows live entirely inside this warp's quad)
        float mx0 = -1e30f, mx8 = -1e30f;
        #pragma unroll
        for (int n = 0; n < 16; n++) {
            mx0 = fmaxf(mx0, fmaxf(c[n][0], c[n][1]));
            mx8 = fmaxf(mx8, fmaxf(c[n][2], c[n][3]));
        }
        mx0 = fmaxf(mx0, __shfl_xor_sync(0xffffffffu, mx0, 1));
        mx0 = fmaxf(mx0, __shfl_xor_sync(0xffffffffu, mx0, 2));
        mx8 = fmaxf(mx8, __shfl_xor_sync(0xffffffffu, mx8, 1));
        mx8 = fmaxf(mx8, __shfl_xor_sync(0xffffffffu, mx8, 2));
        float mn0 = fmaxf(m0, mx0), mn8 = fmaxf(m8, mx8);
        float s0 = 0.f, s8 = 0.f;
        #pragma unroll
        for (int n = 0; n < 16; n++) {
            s0 += __expf(c[n][0] - mn0) + __expf(c[n][1] - mn0);
            s8 += __expf(c[n][2] - mn8) + __expf(c[n][3] - mn8);
        }
        s0 += __shfl_xor_sync(0xffffffffu, s0, 1);
        s0 += __shfl_xor_sync(0xffffffffu, s0, 2);
        s8 += __shfl_xor_sync(0xffffffffu, s8, 1);
        s8 += __shfl_xor_sync(0xffffffffu, s8, 2);
        l0 = l0 * __expf(m0 - mn0) + s0;
        l8 = l8 * __expf(m8 - mn8) + s8;
        m0 = mn0; m8 = mn8;
    }

    if (qd == 0) {
        ms[row0 + g] = m0;     ls[row0 + g] = l0;
        ms[row0 + g + 8] = m8; ls[row0 + g + 8] = l8;
    }
    __syncthreads();

    // ---- phase 2: normalize scores -> attn (in place), O = P V ----
    float o[8][4];
    #pragma unroll
    for (int n = 0; n < 8; n++) { o[n][0]=0.f; o[n][1]=0.f; o[n][2]=0.f; o[n][3]=0.f; }

    for (int kt = 0; kt < SLEN / TK; kt++) {
        __syncthreads();  // previous iteration's mma reads of ps/vs done
        // load V tile
        const float4* vg4 = (const float4*)(vg + (size_t)kt * TK * HD);
        #pragma unroll
        for (int i = 0; i < 8; i++) {
            int vv = tid + i * NTHREADS;
            int r = vv >> 4, c4 = vv & 15;
            float4 t = vg4[vv];
            uint32_t* dst = (uint32_t*)&vs[r * PAD + c4 * 4];
            dst[0] = f2tf32(t.x); dst[1] = f2tf32(t.y);
            dst[2] = f2tf32(t.z); dst[3] = f2tf32(t.w);
        }
        // read raw scores, write normalized attn in place, stage P in smem
        #pragma unroll
        for (int i = 0; i < 16; i++) {
            int vv = tid + i * NTHREADS;  // 4096 float4s = 128x128
            int r = vv >> 5, c4 = vv & 31;
            float mrow = ms[r];
            float inv = 1.0f / ls[r];
            float* gp = ag + (size_t)(q0 + r) * SLEN + kt * TK + c4 * 4;
            float4 t = *(float4*)gp;
            t.x = __expf(t.x - mrow) * inv;
            t.y = __expf(t.y - mrow) * inv;
            t.z = __expf(t.z - mrow) * inv;
            t.w = __expf(t.w - mrow) * inv;
            *(float4*)gp = t;
            uint32_t* dst = (uint32_t*)&ps[r * PADP + c4 * 4];
            dst[0] = f2tf32(t.x); dst[1] = f2tf32(t.y);
            dst[2] = f2tf32(t.z); dst[3] = f2tf32(t.w);
        }
        __syncthreads();

        const uint32_t* psu = (const uint32_t*)ps;
        const uint32_t* vsu = (const uint32_t*)vs;
        #pragma unroll
        for (int kk = 0; kk < 16; kk++) {
            uint32_t a0 = psu[(row0 + g)     * PADP + kk * 8 + qd];
            uint32_t a1 = psu[(row0 + g + 8) * PADP + kk * 8 + qd];
            uint32_t a2 = psu[(row0 + g)     * PADP + kk * 8 + qd + 4];
            uint32_t a3 = psu[(row0 + g + 8) * PADP + kk * 8 + qd + 4];
            #pragma unroll
            for (int n = 0; n < 8; n++) {
                uint32_t b0 = vsu[(kk * 8 + qd)     * PAD + n * 8 + g];
                uint32_t b1 = vsu[(kk * 8 + qd + 4) * PAD + n * 8 + g];
                mma_tf32(o[n], a0, a1, a2, a3, b0, b1);
            }
        }
    }

    // ---- write O ----
    float* orow0 = og + (size_t)(q0 + row0 + g) * HD;
    float* orow8 = orow0 + (size_t)8 * HD;
    #pragma unroll
    for (int n = 0; n < 8; n++) {
        int col = n * 8 + qd * 2;
        *(float2*)(orow0 + col) = make_float2(o[n][0], o[n][1]);
        *(float2*)(orow8 + col) = make_float2(o[n][2], o[n][3]);
    }
}

extern "C" void kernel_launch(void* const* d_in, const int* in_sizes, int n_in,
                              void* d_out, int out_size)
{
    const float* q = (const float*)d_in[0];
    const float* k = (const float*)d_in[1];
    const float* v = (const float*)d_in[2];
    float* out  = (float*)d_out;
    float* attn = out + (size_t)NBH * SLEN * HD;  // output first, then attn

    cudaFuncSetAttribute(sdpa_kernel, cudaFuncAttributeMaxDynamicSharedMemorySize, SMEM_BYTES);
    dim3 grid(SLEN / TQ, NBH);  // 16 q-tiles x 64 batch-heads
    sdpa_kernel<<<grid, NTHREADS, SMEM_BYTES>>>(q, k, v, out, attn);
}

// round 2
// speedup vs baseline: 1.6640x; 1.6640x over previous
#include <cuda_runtime.h>
#include <cstdint>
#include <cstddef>

#define SLEN 2048
#define HD 64
#define NBH 64
#define TQ 128
#define TK 128
#define PAD 68    // qs/ks row stride (floats): banks 4g+qd -> conflict-free
#define PADV 72   // vs row stride: banks 8qd+g -> conflict-free b-frags
#define PADP 132  // ps row stride
#define NTHREADS 256

// smem (floats):
//  region [0, 26112): phase1: qs[128*68]=8704 | ks[128*68]=8704 | pmax[256] | psum[256]
//                     phase2: ps[128*132]=16896 | vs[128*72]=9216
//  tm[16*128]=2048 at 26112  (per-tile row max, persists phase1->2)
//  ms[128], ls[128] at 28160
#define REGION 26112
#define PMAX_OFF (TQ*PAD + TK*PAD)        // 17408
#define PSUM_OFF (PMAX_OFF + 256)         // 17664
#define SMEM_FLOATS (REGION + 16*TQ + 2*TQ)   // 28416
#define SMEM_BYTES (SMEM_FLOATS * 4)          // 113664

__device__ __forceinline__ uint32_t f2tf32(float f) {
    uint32_t u;
    asm("cvt.rna.tf32.f32 %0, %1;\n" : "=r"(u) : "f"(f));
    return u;
}

__device__ __forceinline__ void mma_tf32(float c[4],
    uint32_t a0, uint32_t a1, uint32_t a2, uint32_t a3,
    uint32_t b0, uint32_t b1)
{
    asm volatile(
        "mma.sync.aligned.m16n8k8.row.col.f32.tf32.tf32.f32 "
        "{%0,%1,%2,%3}, {%4,%5,%6,%7}, {%8,%9}, {%0,%1,%2,%3};\n"
        : "+f"(c[0]), "+f"(c[1]), "+f"(c[2]), "+f"(c[3])
        : "r"(a0), "r"(a1), "r"(a2), "r"(a3), "r"(b0), "r"(b1));
}

__global__ __launch_bounds__(NTHREADS, 2)
void sdpa_kernel(const float* __restrict__ q, const float* __restrict__ k,
                 const float* __restrict__ v, float* __restrict__ out,
                 float* __restrict__ attn)
{
    extern __shared__ float smem[];
    float* qs = smem;                   // phase1 [128][68]
    float* ks = smem + TQ * PAD;        // phase1 [128][68]
    float* pmax = smem + PMAX_OFF;      // phase1 [2][128]
    float* psum = smem + PSUM_OFF;      // phase1 [2][128]
    float* ps = smem;                   // phase2 [128][132]
    float* vs = smem + TQ * PADP;       // phase2 [128][72]
    float* tm = smem + REGION;          // [16][128]
    float* ms = tm + 16 * TQ;           // [128]
    float* ls = ms + TQ;                // [128] (stores 1/l)

    const int qt = blockIdx.x;
    const int bh = blockIdx.y;
    const int q0 = qt * TQ;
    const int tid = threadIdx.x;
    const int lane = tid & 31;
    const int warp = tid >> 5;
    const int g = lane >> 2;    // 0..7
    const int qd = lane & 3;    // 0..3
    const int wr = warp >> 1;   // 0..3 row-group (32 rows)
    const int wc = warp & 1;    // 0..1 col-group
    const int rbase = wr * 32;

    const float* qg = q + (size_t)bh * SLEN * HD;
    const float* kg = k + (size_t)bh * SLEN * HD;
    const float* vg = v + (size_t)bh * SLEN * HD;
    float* og = out + (size_t)bh * SLEN * HD;
    float* ag = attn + (size_t)bh * SLEN * SLEN;

    // ---- load Q tile (pre-scaled by 1/temperature), tf32-rounded ----
    {
        const float4* qg4 = (const float4*)(qg + (size_t)q0 * HD);
        #pragma unroll
        for (int i = 0; i < 8; i++) {
            int vv = tid + i * NTHREADS;        // 2048 float4s = 128x64
            int r = vv >> 4, c4 = vv & 15;
            float4 t = qg4[vv];
            uint32_t* dst = (uint32_t*)&qs[r * PAD + c4 * 4];
            dst[0] = f2tf32(t.x * 0.125f);
            dst[1] = f2tf32(t.y * 0.125f);
            dst[2] = f2tf32(t.z * 0.125f);
            dst[3] = f2tf32(t.w * 0.125f);
        }
    }

    // ---- phase 1: S = Q K^T; write e = exp(s - m_tile) to attn scratch ----
    float m_run[4] = {-1e30f, -1e30f, -1e30f, -1e30f};
    float l_run[4] = {0.f, 0.f, 0.f, 0.f};

    for (int kt = 0; kt < SLEN / TK; kt++) {
        __syncthreads();  // prior reads of ks complete
        const float4* kg4 = (const float4*)(kg + (size_t)kt * TK * HD);
        #pragma unroll
        for (int i = 0; i < 8; i++) {
            int vv = tid + i * NTHREADS;
            int r = vv >> 4, c4 = vv & 15;
            float4 t = kg4[vv];
            uint32_t* dst = (uint32_t*)&ks[r * PAD + c4 * 4];
            dst[0] = f2tf32(t.x); dst[1] = f2tf32(t.y);
            dst[2] = f2tf32(t.z); dst[3] = f2tf32(t.w);
        }
        __syncthreads();

        // 2D warp tile: 32 rows x 64 cols, c[mi][n][4]
        float c[2][8][4];
        #pragma unroll
        for (int mi = 0; mi < 2; mi++)
            #pragma unroll
            for (int n = 0; n < 8; n++)
                { c[mi][n][0]=0.f; c[mi][n][1]=0.f; c[mi][n][2]=0.f; c[mi][n][3]=0.f; }

        const uint32_t* qsu = (const uint32_t*)qs;
        const uint32_t* ksu = (const uint32_t*)ks;
        #pragma unroll
        for (int kk = 0; kk < 8; kk++) {
            uint32_t a[2][4];
            #pragma unroll
            for (int mi = 0; mi < 2; mi++) {
                int r = rbase + mi * 16 + g;
                a[mi][0] = qsu[r * PAD + kk * 8 + qd];
                a[mi][1] = qsu[(r + 8) * PAD + kk * 8 + qd];
                a[mi][2] = qsu[r * PAD + kk * 8 + qd + 4];
                a[mi][3] = qsu[(r + 8) * PAD + kk * 8 + qd + 4];
            }
            #pragma unroll
            for (int n = 0; n < 8; n++) {
                int cc = wc * 64 + n * 8 + g;
                uint32_t b0 = ksu[cc * PAD + kk * 8 + qd];
                uint32_t b1 = ksu[cc * PAD + kk * 8 + qd + 4];
                mma_tf32(c[0][n], a[0][0], a[0][1], a[0][2], a[0][3], b0, b1);
                mma_tf32(c[1][n], a[1][0], a[1][1], a[1][2], a[1][3], b0, b1);
            }
        }

        // warp-local row max over this warp's 64 cols (j -> row rbase+j*8+g)
        float mx[4] = {-1e30f, -1e30f, -1e30f, -1e30f};
        #pragma unroll
        for (int n = 0; n < 8; n++) {
            mx[0] = fmaxf(mx[0], fmaxf(c[0][n][0], c[0][n][1]));
            mx[1] = fmaxf(mx[1], fmaxf(c[0][n][2], c[0][n][3]));
            mx[2] = fmaxf(mx[2], fmaxf(c[1][n][0], c[1][n][1]));
            mx[3] = fmaxf(mx[3], fmaxf(c[1][n][2], c[1][n][3]));
        }
        #pragma unroll
        for (int j = 0; j < 4; j++) {
            mx[j] = fmaxf(mx[j], __shfl_xor_sync(0xffffffffu, mx[j], 1));
            mx[j] = fmaxf(mx[j], __shfl_xor_sync(0xffffffffu, mx[j], 2));
        }
        if (qd == 0) {
            #pragma unroll
            for (int j = 0; j < 4; j++)
                pmax[wc * 128 + rbase + j * 8 + g] = mx[j];
        }
        __syncthreads();

        float mn[4];
        #pragma unroll
        for (int j = 0; j < 4; j++) {
            int r = rbase + j * 8 + g;
            float full = fmaxf(pmax[r], pmax[128 + r]);
            mn[j] = fmaxf(m_run[j], full);
        }

        // e = exp(s - mn), store to attn scratch, partial row sums
        float sum[4] = {0.f, 0.f, 0.f, 0.f};
        float* arow = ag + (size_t)(q0 + rbase + g) * SLEN + kt * TK + wc * 64;
        #pragma unroll
        for (int n = 0; n < 8; n++) {
            int col = n * 8 + qd * 2;
            float e0 = __expf(c[0][n][0] - mn[0]);
            float e1 = __expf(c[0][n][1] - mn[0]);
            float e2 = __expf(c[0][n][2] - mn[1]);
            float e3 = __expf(c[0][n][3] - mn[1]);
            sum[0] += e0 + e1; sum[1] += e2 + e3;
            *(float2*)(arow + col) = make_float2(e0, e1);
            *(float2*)(arow + (size_t)8 * SLEN + col) = make_float2(e2, e3);
            float f0 = __expf(c[1][n][0] - mn[2]);
            float f1 = __expf(c[1][n][1] - mn[2]);
            float f2 = __expf(c[1][n][2] - mn[3]);
            float f3 = __expf(c[1][n][3] - mn[3]);
            sum[2] += f0 + f1; sum[3] += f2 + f3;
            *(float2*)(arow + (size_t)16 * SLEN + col) = make_float2(f0, f1);
            *(float2*)(arow + (size_t)24 * SLEN + col) = make_float2(f2, f3);
        }
        #pragma unroll
        for (int j = 0; j < 4; j++) {
            sum[j] += __shfl_xor_sync(0xffffffffu, sum[j], 1);
            sum[j] += __shfl_xor_sync(0xffffffffu, sum[j], 2);
        }
        if (qd == 0) {
            #pragma unroll
            for (int j = 0; j < 4; j++)
                psum[wc * 128 + rbase + j * 8 + g] = sum[j];
        }
        __syncthreads();

        #pragma unroll
        for (int j = 0; j < 4; j++) {
            int r = rbase + j * 8 + g;
            float tot = psum[r] + psum[128 + r];
            l_run[j] = l_run[j] * __expf(m_run[j] - mn[j]) + tot;
            m_run[j] = mn[j];
        }
        if (qd == 0 && wc == 0) {
            #pragma unroll
            for (int j = 0; j < 4; j++)
                tm[kt * 128 + rbase + j * 8 + g] = mn[j];
        }
    }

    if (qd == 0 && wc == 0) {
        #pragma unroll
        for (int j = 0; j < 4; j++) {
            int r = rbase + j * 8 + g;
            ms[r] = m_run[j];
            ls[r] = __frcp_rn(l_run[j]);
        }
    }

    // ---- phase 2: attn = e * exp(tm - m)/l (in place); O = P V ----
    float o[2][4][4];
    #pragma unroll
    for (int mi = 0; mi < 2; mi++)
        #pragma unroll
        for (int n = 0; n < 4; n++)
            { o[mi][n][0]=0.f; o[mi][n][1]=0.f; o[mi][n][2]=0.f; o[mi][n][3]=0.f; }

    for (int kt = 0; kt < SLEN / TK; kt++) {
        __syncthreads();  // prior mma reads of ps/vs done (also closes phase1)
        // V tile -> vs (PADV=72)
        const float4* vg4 = (const float4*)(vg + (size_t)kt * TK * HD);
        #pragma unroll
        for (int i = 0; i < 8; i++) {
            int vv = tid + i * NTHREADS;
            int r = vv >> 4, c4 = vv & 15;
            float4 t = vg4[vv];
            uint32_t* dst = (uint32_t*)&vs[r * PADV + c4 * 4];
            dst[0] = f2tf32(t.x); dst[1] = f2tf32(t.y);
            dst[2] = f2tf32(t.z); dst[3] = f2tf32(t.w);
        }
        // read e, scale -> attn (in place), stage P in smem (no exp here)
        #pragma unroll
        for (int i = 0; i < 16; i++) {
            int vv = tid + i * NTHREADS;  // 4096 float4s = 128x128
            int r = vv >> 5, c4 = vv & 31;
            float factor = __expf(tm[kt * 128 + r] - ms[r]) * ls[r];
            float* gp = ag + (size_t)(q0 + r) * SLEN + kt * TK + c4 * 4;
            float4 t = *(float4*)gp;
            t.x *= factor; t.y *= factor; t.z *= factor; t.w *= factor;
            *(float4*)gp = t;
            uint32_t* dst = (uint32_t*)&ps[r * PADP + c4 * 4];
            dst[0] = f2tf32(t.x); dst[1] = f2tf32(t.y);
            dst[2] = f2tf32(t.z); dst[3] = f2tf32(t.w);
        }
        __syncthreads();

        const uint32_t* psu = (const uint32_t*)ps;
        const uint32_t* vsu = (const uint32_t*)vs;
        #pragma unroll
        for (int kk = 0; kk < 16; kk++) {
            uint32_t a[2][4];
            #pragma unroll
            for (int mi = 0; mi < 2; mi++) {
                int r = rbase + mi * 16 + g;
                a[mi][0] = psu[r * PADP + kk * 8 + qd];
                a[mi][1] = psu[(r + 8) * PADP + kk * 8 + qd];
                a[mi][2] = psu[r * PADP + kk * 8 + qd + 4];
                a[mi][3] = psu[(r + 8) * PADP + kk * 8 + qd + 4];
            }
            #pragma unroll
            for (int n = 0; n < 4; n++) {
                int cc = wc * 32 + n * 8 + g;
                uint32_t b0 = vsu[(kk * 8 + qd) * PADV + cc];
                uint32_t b1 = vsu[(kk * 8 + qd + 4) * PADV + cc];
                mma_tf32(o[0][n], a[0][0], a[0][1], a[0][2], a[0][3], b0, b1);
                mma_tf32(o[1][n], a[1][0], a[1][1], a[1][2], a[1][3], b0, b1);
            }
        }
    }

    // ---- write O: rows rbase+mi*16+{g,g+8}, cols wc*32+n*8+qd*2 ----
    #pragma unroll
    for (int mi = 0; mi < 2; mi++) {
        float* orow = og + (size_t)(q0 + rbase + mi * 16 + g) * HD + wc * 32;
        #pragma unroll
        for (int n = 0; n < 4; n++) {
            int col = n * 8 + qd * 2;
            *(float2*)(orow + col) = make_float2(o[mi][n][0], o[mi][n][1]);
            *(float2*)(orow + (size_t)8 * HD + col) = make_float2(o[mi][n][2], o[mi][n][3]);
        }
    }
}

extern "C" void kernel_launch(void* const* d_in, const int* in_sizes, int n_in,
                              void* d_out, int out_size)
{
    const float* q = (const float*)d_in[0];
    const float* k = (const float*)d_in[1];
    const float* v = (const float*)d_in[2];
    float* out  = (float*)d_out;
    float* attn = out + (size_t)NBH * SLEN * HD;  // output first, then attn

    cudaFuncSetAttribute(sdpa_kernel, cudaFuncAttributeMaxDynamicSharedMemorySize, SMEM_BYTES);
    dim3 grid(SLEN / TQ, NBH);  // 16 q-tiles x 64 batch-heads
    sdpa_kernel<<<grid, NTHREADS, SMEM_BYTES>>>(q, k, v, out, attn);
}

// round 3
// speedup vs baseline: 2.4480x; 1.4711x over previous
#include <cuda_runtime.h>
#include <cstdint>
#include <cstddef>

#define SLEN 2048
#define HD 64
#define NBH 64
#define TQ 128
#define TKV 64
#define PAD 68    // qs/ks row stride (floats)
#define PADV 72   // vs row stride
#define PADP 36   // per-warp e-staging row stride
#define NTHREADS 256

// per-row log(sum exp(s)) scratch
__device__ float g_lnl[(size_t)NBH * SLEN];

// ---------------- kernel 1 smem layout (floats) ----------------
// qs[128*68]=8704 | ks[64*68]=4352 | vs[64*72]=4608 | ps[8*32*36]=9216
// lpart[256] | ls[128]   ; obuf[128*68]=8704 aliases ks.. after main loop
#define K1_QS 0
#define K1_KS 8704
#define K1_VS 13056
#define K1_PS 17664
#define K1_LP 26880
#define K1_LS 27136
#define K1_OB 8704
#define K1_SMEM_FLOATS 27264
#define K1_SMEM_BYTES (K1_SMEM_FLOATS * 4)

// ---------------- kernel 2 smem layout ----------------
#define K2_QS 0
#define K2_KS 8704
#define K2_SMEM_FLOATS 13056
#define K2_SMEM_BYTES (K2_SMEM_FLOATS * 4)

__device__ __forceinline__ uint32_t f2tf32(float f) {
    uint32_t u;
    asm("cvt.rna.tf32.f32 %0, %1;\n" : "=r"(u) : "f"(f));
    return u;
}

__device__ __forceinline__ void mma_tf32(float c[4],
    uint32_t a0, uint32_t a1, uint32_t a2, uint32_t a3,
    uint32_t b0, uint32_t b1)
{
    asm volatile(
        "mma.sync.aligned.m16n8k8.row.col.f32.tf32.tf32.f32 "
        "{%0,%1,%2,%3}, {%4,%5,%6,%7}, {%8,%9}, {%0,%1,%2,%3};\n"
        : "+f"(c[0]), "+f"(c[1]), "+f"(c[2]), "+f"(c[3])
        : "r"(a0), "r"(a1), "r"(a2), "r"(a3), "r"(b0), "r"(b1));
}

// ============ kernel 1: flash fwd (no attn write), O and log-l ============
__global__ __launch_bounds__(NTHREADS, 2)
void sdpa_flash(const float* __restrict__ q, const float* __restrict__ k,
                const float* __restrict__ v, float* __restrict__ out)
{
    extern __shared__ float smem[];
    float* qs = smem + K1_QS;
    float* ks = smem + K1_KS;
    float* vs = smem + K1_VS;
    float* ps = smem + K1_PS;
    float* lpart = smem + K1_LP;
    float* ls = smem + K1_LS;
    float* obuf = smem + K1_OB;

    const int qt = blockIdx.x, bh = blockIdx.y;
    const int q0 = qt * TQ;
    const int tid = threadIdx.x;
    const int lane = tid & 31, warp = tid >> 5;
    const int g = lane >> 2, qd = lane & 3;
    const int wr = warp >> 1, wc = warp & 1;
    const int rbase = wr * 32;

    const float* qg = q + (size_t)bh * SLEN * HD;
    const float* kg = k + (size_t)bh * SLEN * HD;
    const float* vg = v + (size_t)bh * SLEN * HD;
    float* og = out + (size_t)bh * SLEN * HD;

    // Q tile (scaled by 1/8), tf32
    {
        const float4* qg4 = (const float4*)(qg + (size_t)q0 * HD);
        #pragma unroll
        for (int i = 0; i < 8; i++) {
            int vv = tid + i * NTHREADS;       // 2048 float4 = 128x64
            int r = vv >> 4, c4 = vv & 15;
            float4 t = qg4[vv];
            uint32_t* dst = (uint32_t*)&qs[r * PAD + c4 * 4];
            dst[0] = f2tf32(t.x * 0.125f);
            dst[1] = f2tf32(t.y * 0.125f);
            dst[2] = f2tf32(t.z * 0.125f);
            dst[3] = f2tf32(t.w * 0.125f);
        }
    }

    float lsum[4] = {0.f, 0.f, 0.f, 0.f};
    float o[2][8][4];
    #pragma unroll
    for (int mi = 0; mi < 2; mi++)
        #pragma unroll
        for (int n = 0; n < 8; n++)
            { o[mi][n][0]=0.f; o[mi][n][1]=0.f; o[mi][n][2]=0.f; o[mi][n][3]=0.f; }

    const uint32_t wb = warp * (32 * PADP);
    uint32_t* psw = (uint32_t*)ps;

    for (int kt = 0; kt < SLEN / TKV; kt++) {
        __syncthreads();
        // K,V tiles 64x64 -> smem tf32
        const float4* kg4 = (const float4*)(kg + (size_t)kt * TKV * HD);
        const float4* vg4 = (const float4*)(vg + (size_t)kt * TKV * HD);
        #pragma unroll
        for (int i = 0; i < 4; i++) {
            int vv = tid + i * NTHREADS;       // 1024 float4 = 64x64
            int r = vv >> 4, c4 = vv & 15;
            float4 t = kg4[vv];
            uint32_t* dst = (uint32_t*)&ks[r * PAD + c4 * 4];
            dst[0] = f2tf32(t.x); dst[1] = f2tf32(t.y);
            dst[2] = f2tf32(t.z); dst[3] = f2tf32(t.w);
            float4 u = vg4[vv];
            uint32_t* dv = (uint32_t*)&vs[r * PADV + c4 * 4];
            dv[0] = f2tf32(u.x); dv[1] = f2tf32(u.y);
            dv[2] = f2tf32(u.z); dv[3] = f2tf32(u.w);
        }
        __syncthreads();

        // QK: warp tile 32 rows x 32 cols
        float c[2][4][4];
        #pragma unroll
        for (int mi = 0; mi < 2; mi++)
            #pragma unroll
            for (int n = 0; n < 4; n++)
                { c[mi][n][0]=0.f; c[mi][n][1]=0.f; c[mi][n][2]=0.f; c[mi][n][3]=0.f; }

        const uint32_t* qsu = (const uint32_t*)qs;
        const uint32_t* ksu = (const uint32_t*)ks;
        #pragma unroll
        for (int kk = 0; kk < 8; kk++) {
            uint32_t a[2][4];
            #pragma unroll
            for (int mi = 0; mi < 2; mi++) {
                int r = rbase + mi * 16 + g;
                a[mi][0] = qsu[r * PAD + kk * 8 + qd];
                a[mi][1] = qsu[(r + 8) * PAD + kk * 8 + qd];
                a[mi][2] = qsu[r * PAD + kk * 8 + qd + 4];
                a[mi][3] = qsu[(r + 8) * PAD + kk * 8 + qd + 4];
            }
            #pragma unroll
            for (int n = 0; n < 4; n++) {
                int cc = wc * 32 + n * 8 + g;
                uint32_t b0 = ksu[cc * PAD + kk * 8 + qd];
                uint32_t b1 = ksu[cc * PAD + kk * 8 + qd + 4];
                mma_tf32(c[0][n], a[0][0], a[0][1], a[0][2], a[0][3], b0, b1);
                mma_tf32(c[1][n], a[1][0], a[1][1], a[1][2], a[1][3], b0, b1);
            }
        }

        // e = exp(s); accumulate l; stage e (tf32) in per-warp block
        #pragma unroll
        for (int mi = 0; mi < 2; mi++) {
            int lr = mi * 16 + g;
            #pragma unroll
            for (int n = 0; n < 4; n++) {
                float e0 = __expf(c[mi][n][0]);
                float e1 = __expf(c[mi][n][1]);
                float e2 = __expf(c[mi][n][2]);
                float e3 = __expf(c[mi][n][3]);
                lsum[2 * mi]     += e0 + e1;
                lsum[2 * mi + 1] += e2 + e3;
                psw[wb + lr * PADP + n * 8 + 2 * qd]         = f2tf32(e0);
                psw[wb + lr * PADP + n * 8 + 2 * qd + 1]     = f2tf32(e1);
                psw[wb + (lr + 8) * PADP + n * 8 + 2 * qd]     = f2tf32(e2);
                psw[wb + (lr + 8) * PADP + n * 8 + 2 * qd + 1] = f2tf32(e3);
            }
        }
        __syncwarp();

        // PV: o += e(32xk32) * V(k32 x 64)
        const uint32_t* vsu = (const uint32_t*)vs;
        #pragma unroll
        for (int kk2 = 0; kk2 < 4; kk2++) {
            uint32_t a[2][4];
            #pragma unroll
            for (int mi = 0; mi < 2; mi++) {
                int lr = mi * 16 + g;
                a[mi][0] = psw[wb + lr * PADP + kk2 * 8 + qd];
                a[mi][1] = psw[wb + (lr + 8) * PADP + kk2 * 8 + qd];
                a[mi][2] = psw[wb + lr * PADP + kk2 * 8 + qd + 4];
                a[mi][3] = psw[wb + (lr + 8) * PADP + kk2 * 8 + qd + 4];
            }
            int vr = wc * 32 + kk2 * 8 + qd;
            #pragma unroll
            for (int n = 0; n < 8; n++) {
                uint32_t b0 = vsu[vr * PADV + n * 8 + g];
                uint32_t b1 = vsu[(vr + 4) * PADV + n * 8 + g];
                mma_tf32(o[0][n], a[0][0], a[0][1], a[0][2], a[0][3], b0, b1);
                mma_tf32(o[1][n], a[1][0], a[1][1], a[1][2], a[1][3], b0, b1);
            }
        }
    }

    // reduce l across quad, then across wc halves
    #pragma unroll
    for (int j = 0; j < 4; j++) {
        lsum[j] += __shfl_xor_sync(0xffffffffu, lsum[j], 1);
        lsum[j] += __shfl_xor_sync(0xffffffffu, lsum[j], 2);
    }
    if (qd == 0) {
        #pragma unroll
        for (int j = 0; j < 4; j++) {
            int row = rbase + (j >> 1) * 16 + (j & 1) * 8 + g;
            lpart[wc * 128 + row] = lsum[j];
        }
    }
    __syncthreads();
    if (tid < TQ) {
        float L = lpart[tid] + lpart[128 + tid];
        ls[tid] = __frcp_rn(L);
        g_lnl[(size_t)bh * SLEN + q0 + tid] = __logf(L);
    }
    __syncthreads();

    // combine O across wc halves, scale, store
    if (wc == 1) {
        #pragma unroll
        for (int mi = 0; mi < 2; mi++) {
            int row = rbase + mi * 16 + g;
            #pragma unroll
            for (int n = 0; n < 8; n++) {
                obuf[row * PAD + n * 8 + 2 * qd]     = o[mi][n][0];
                obuf[row * PAD + n * 8 + 2 * qd + 1] = o[mi][n][1];
                obuf[(row + 8) * PAD + n * 8 + 2 * qd]     = o[mi][n][2];
                obuf[(row + 8) * PAD + n * 8 + 2 * qd + 1] = o[mi][n][3];
            }
        }
    }
    __syncthreads();
    if (wc == 0) {
        #pragma unroll
        for (int mi = 0; mi < 2; mi++) {
            int row = rbase + mi * 16 + g;
            float inv0 = ls[row], inv1 = ls[row + 8];
            float* orow0 = og + (size_t)(q0 + row) * HD;
            float* orow1 = orow0 + (size_t)8 * HD;
            #pragma unroll
            for (int n = 0; n < 8; n++) {
                int col = n * 8 + 2 * qd;
                float x0 = (o[mi][n][0] + obuf[row * PAD + col]) * inv0;
                float x1 = (o[mi][n][1] + obuf[row * PAD + col + 1]) * inv0;
                float x2 = (o[mi][n][2] + obuf[(row + 8) * PAD + col]) * inv1;
                float x3 = (o[mi][n][3] + obuf[(row + 8) * PAD + col + 1]) * inv1;
                *(float2*)(orow0 + col) = make_float2(x0, x1);
                *(float2*)(orow1 + col) = make_float2(x2, x3);
            }
        }
    }
}

// ============ kernel 2: recompute S, write attn = exp(s - lnl) ============
__global__ __launch_bounds__(NTHREADS, 3)
void sdpa_attn(const float* __restrict__ q, const float* __restrict__ k,
               float* __restrict__ attn)
{
    extern __shared__ float smem[];
    float* qs = smem + K2_QS;
    float* ks = smem + K2_KS;

    const int qt = blockIdx.x, bh = blockIdx.y;
    const int q0 = qt * TQ;
    const int tid = threadIdx.x;
    const int lane = tid & 31, warp = tid >> 5;
    const int g = lane >> 2, qd = lane & 3;
    const int wr = warp >> 1, wc = warp & 1;
    const int rbase = wr * 32;

    const float* qg = q + (size_t)bh * SLEN * HD;
    const float* kg = k + (size_t)bh * SLEN * HD;
    float* ag = attn + (size_t)bh * SLEN * SLEN;

    {
        const float4* qg4 = (const float4*)(qg + (size_t)q0 * HD);
        #pragma unroll
        for (int i = 0; i < 8; i++) {
            int vv = tid + i * NTHREADS;
            int r = vv >> 4, c4 = vv & 15;
            float4 t = qg4[vv];
            uint32_t* dst = (uint32_t*)&qs[r * PAD + c4 * 4];
            dst[0] = f2tf32(t.x * 0.125f);
            dst[1] = f2tf32(t.y * 0.125f);
            dst[2] = f2tf32(t.z * 0.125f);
            dst[3] = f2tf32(t.w * 0.125f);
        }
    }

    // per-thread row lnl (4 rows)
    float lnl[4];
    #pragma unroll
    for (int j = 0; j < 4; j++) {
        int row = rbase + (j >> 1) * 16 + (j & 1) * 8 + g;
        lnl[j] = g_lnl[(size_t)bh * SLEN + q0 + row];
    }

    for (int kt = 0; kt < SLEN / TKV; kt++) {
        __syncthreads();
        const float4* kg4 = (const float4*)(kg + (size_t)kt * TKV * HD);
        #pragma unroll
        for (int i = 0; i < 4; i++) {
            int vv = tid + i * NTHREADS;
            int r = vv >> 4, c4 = vv & 15;
            float4 t = kg4[vv];
            uint32_t* dst = (uint32_t*)&ks[r * PAD + c4 * 4];
            dst[0] = f2tf32(t.x); dst[1] = f2tf32(t.y);
            dst[2] = f2tf32(t.z); dst[3] = f2tf32(t.w);
        }
        __syncthreads();

        float c[2][4][4];
        #pragma unroll
        for (int mi = 0; mi < 2; mi++)
            #pragma unroll
            for (int n = 0; n < 4; n++)
                { c[mi][n][0]=0.f; c[mi][n][1]=0.f; c[mi][n][2]=0.f; c[mi][n][3]=0.f; }

        const uint32_t* qsu = (const uint32_t*)qs;
        const uint32_t* ksu = (const uint32_t*)ks;
        #pragma unroll
        for (int kk = 0; kk < 8; kk++) {
            uint32_t a[2][4];
            #pragma unroll
            for (int mi = 0; mi < 2; mi++) {
                int r = rbase + mi * 16 + g;
                a[mi][0] = qsu[r * PAD + kk * 8 + qd];
                a[mi][1] = qsu[(r + 8) * PAD + kk * 8 + qd];
                a[mi][2] = qsu[r * PAD + kk * 8 + qd + 4];
                a[mi][3] = qsu[(r + 8) * PAD + kk * 8 + qd + 4];
            }
            #pragma unroll
            for (int n = 0; n < 4; n++) {
                int cc = wc * 32 + n * 8 + g;
                uint32_t b0 = ksu[cc * PAD + kk * 8 + qd];
                uint32_t b1 = ksu[cc * PAD + kk * 8 + qd + 4];
                mma_tf32(c[0][n], a[0][0], a[0][1], a[0][2], a[0][3], b0, b1);
                mma_tf32(c[1][n], a[1][0], a[1][1], a[1][2], a[1][3], b0, b1);
            }
        }

        // attn = exp(s - lnl), streaming store
        #pragma unroll
        for (int mi = 0; mi < 2; mi++) {
            int row = rbase + mi * 16 + g;
            float* ar0 = ag + (size_t)(q0 + row) * SLEN + kt * TKV + wc * 32;
            float* ar1 = ar0 + (size_t)8 * SLEN;
            float l0 = lnl[2 * mi], l1 = lnl[2 * mi + 1];
            #pragma unroll
            for (int n = 0; n < 4; n++) {
                int col = n * 8 + 2 * qd;
                float p0 = __expf(c[mi][n][0] - l0);
                float p1 = __expf(c[mi][n][1] - l0);
                float p2 = __expf(c[mi][n][2] - l1);
                float p3 = __expf(c[mi][n][3] - l1);
                *(float2*)(ar0 + col) = make_float2(p0, p1);
                *(float2*)(ar1 + col) = make_float2(p2, p3);
            }
        }
    }
}

extern "C" void kernel_launch(void* const* d_in, const int* in_sizes, int n_in,
                              void* d_out, int out_size)
{
    const float* q = (const float*)d_in[0];
    const float* k = (const float*)d_in[1];
    const float* v = (const float*)d_in[2];
    float* out  = (float*)d_out;
    float* attn = out + (size_t)NBH * SLEN * HD;

    cudaFuncSetAttribute(sdpa_flash, cudaFuncAttributeMaxDynamicSharedMemorySize, K1_SMEM_BYTES);
    cudaFuncSetAttribute(sdpa_attn,  cudaFuncAttributeMaxDynamicSharedMemorySize, K2_SMEM_BYTES);

    dim3 grid(SLEN / TQ, NBH);
    sdpa_flash<<<grid, NTHREADS, K1_SMEM_BYTES>>>(q, k, v, out);
    sdpa_attn<<<grid, NTHREADS, K2_SMEM_BYTES>>>(q, k, attn);
}

// round 4
// speedup vs baseline: 2.4497x; 1.0007x over previous
#include <cuda_runtime.h>
#include <cstdint>
#include <cstddef>

#define SLEN 2048
#define HD 64
#define NBH 64
#define TQ 128
#define TKV 64
#define PAD 68    // qs/ks row stride (floats)
#define PADV 72   // vs row stride
#define PADP 36   // per-warp e-staging row stride
#define NTHREADS 256

// per-row log(sum exp(s)) scratch
__device__ float g_lnl[(size_t)NBH * SLEN];

// ---------------- kernel 1 smem layout (floats) ----------------
#define K1_QS 0
#define K1_KS 8704
#define K1_VS 13056
#define K1_PS 17664
#define K1_LP 26880
#define K1_LS 27136
#define K1_OB 8704
#define K1_SMEM_FLOATS 27264
#define K1_SMEM_BYTES (K1_SMEM_FLOATS * 4)

// ---------------- kernel 2 smem layout ----------------
#define K2_QS 0
#define K2_KS 8704
#define K2_SMEM_FLOATS 13056
#define K2_SMEM_BYTES (K2_SMEM_FLOATS * 4)

__device__ __forceinline__ uint32_t f2tf32(float f) {
    uint32_t u;
    asm("cvt.rna.tf32.f32 %0, %1;\n" : "=r"(u) : "f"(f));
    return u;
}

__device__ __forceinline__ void mma_tf32(float c[4],
    uint32_t a0, uint32_t a1, uint32_t a2, uint32_t a3,
    uint32_t b0, uint32_t b1)
{
    asm volatile(
        "mma.sync.aligned.m16n8k8.row.col.f32.tf32.tf32.f32 "
        "{%0,%1,%2,%3}, {%4,%5,%6,%7}, {%8,%9}, {%0,%1,%2,%3};\n"
        : "+f"(c[0]), "+f"(c[1]), "+f"(c[2]), "+f"(c[3])
        : "r"(a0), "r"(a1), "r"(a2), "r"(a3), "r"(b0), "r"(b1));
}

// ============ kernel 1: flash fwd (no attn write), O and log-l ============
__global__ __launch_bounds__(NTHREADS, 2)
void sdpa_flash(const float* __restrict__ q, const float* __restrict__ k,
                const float* __restrict__ v, float* __restrict__ out)
{
    extern __shared__ float smem[];
    float* qs = smem + K1_QS;
    float* ks = smem + K1_KS;
    float* vs = smem + K1_VS;
    float* ps = smem + K1_PS;
    float* lpart = smem + K1_LP;
    float* ls = smem + K1_LS;
    float* obuf = smem + K1_OB;

    const int qt = blockIdx.x, bh = blockIdx.y;
    const int q0 = qt * TQ;
    const int tid = threadIdx.x;
    const int lane = tid & 31, warp = tid >> 5;
    const int g = lane >> 2, qd = lane & 3;
    const int wr = warp >> 1, wc = warp & 1;
    const int rbase = wr * 32;

    const float* qg = q + (size_t)bh * SLEN * HD;
    const float* kg = k + (size_t)bh * SLEN * HD;
    const float* vg = v + (size_t)bh * SLEN * HD;
    float* og = out + (size_t)bh * SLEN * HD;

    // Q tile (scaled by 1/8), tf32
    {
        const float4* qg4 = (const float4*)(qg + (size_t)q0 * HD);
        #pragma unroll
        for (int i = 0; i < 8; i++) {
            int vv = tid + i * NTHREADS;       // 2048 float4 = 128x64
            int r = vv >> 4, c4 = vv & 15;
            float4 t = qg4[vv];
            uint32_t* dst = (uint32_t*)&qs[r * PAD + c4 * 4];
            dst[0] = f2tf32(t.x * 0.125f);
            dst[1] = f2tf32(t.y * 0.125f);
            dst[2] = f2tf32(t.z * 0.125f);
            dst[3] = f2tf32(t.w * 0.125f);
        }
    }

    float lsum[4] = {0.f, 0.f, 0.f, 0.f};
    float o[2][8][4];
    #pragma unroll
    for (int mi = 0; mi < 2; mi++)
        #pragma unroll
        for (int n = 0; n < 8; n++)
            { o[mi][n][0]=0.f; o[mi][n][1]=0.f; o[mi][n][2]=0.f; o[mi][n][3]=0.f; }

    const uint32_t wb = warp * (32 * PADP);
    uint32_t* psw = (uint32_t*)ps;

    for (int kt = 0; kt < SLEN / TKV; kt++) {
        // prefetch K,V tile into registers BEFORE barrier (global reads
        // have no hazard vs smem; hides LDG latency behind barrier wait)
        const float4* kg4 = (const float4*)(kg + (size_t)kt * TKV * HD);
        const float4* vg4 = (const float4*)(vg + (size_t)kt * TKV * HD);
        float4 kreg[4], vreg[4];
        #pragma unroll
        for (int i = 0; i < 4; i++) {
            int vv = tid + i * NTHREADS;       // 1024 float4 = 64x64
            kreg[i] = kg4[vv];
            vreg[i] = vg4[vv];
        }
        __syncthreads();   // prior iteration reads of ks/vs complete
        #pragma unroll
        for (int i = 0; i < 4; i++) {
            int vv = tid + i * NTHREADS;
            int r = vv >> 4, c4 = vv & 15;
            uint32_t* dst = (uint32_t*)&ks[r * PAD + c4 * 4];
            dst[0] = f2tf32(kreg[i].x); dst[1] = f2tf32(kreg[i].y);
            dst[2] = f2tf32(kreg[i].z); dst[3] = f2tf32(kreg[i].w);
            uint32_t* dv = (uint32_t*)&vs[r * PADV + c4 * 4];
            dv[0] = f2tf32(vreg[i].x); dv[1] = f2tf32(vreg[i].y);
            dv[2] = f2tf32(vreg[i].z); dv[3] = f2tf32(vreg[i].w);
        }
        __syncthreads();

        // QK: warp tile 32 rows x 32 cols
        float c[2][4][4];
        #pragma unroll
        for (int mi = 0; mi < 2; mi++)
            #pragma unroll
            for (int n = 0; n < 4; n++)
                { c[mi][n][0]=0.f; c[mi][n][1]=0.f; c[mi][n][2]=0.f; c[mi][n][3]=0.f; }

        const uint32_t* qsu = (const uint32_t*)qs;
        const uint32_t* ksu = (const uint32_t*)ks;
        #pragma unroll
        for (int kk = 0; kk < 8; kk++) {
            uint32_t a[2][4];
            #pragma unroll
            for (int mi = 0; mi < 2; mi++) {
                int r = rbase + mi * 16 + g;
                a[mi][0] = qsu[r * PAD + kk * 8 + qd];
                a[mi][1] = qsu[(r + 8) * PAD + kk * 8 + qd];
                a[mi][2] = qsu[r * PAD + kk * 8 + qd + 4];
                a[mi][3] = qsu[(r + 8) * PAD + kk * 8 + qd + 4];
            }
            #pragma unroll
            for (int n = 0; n < 4; n++) {
                int cc = wc * 32 + n * 8 + g;
                uint32_t b0 = ksu[cc * PAD + kk * 8 + qd];
                uint32_t b1 = ksu[cc * PAD + kk * 8 + qd + 4];
                mma_tf32(c[0][n], a[0][0], a[0][1], a[0][2], a[0][3], b0, b1);
                mma_tf32(c[1][n], a[1][0], a[1][1], a[1][2], a[1][3], b0, b1);
            }
        }

        // e = exp(s); accumulate l; stage e (tf32) in per-warp block
        #pragma unroll
        for (int mi = 0; mi < 2; mi++) {
            int lr = mi * 16 + g;
            #pragma unroll
            for (int n = 0; n < 4; n++) {
                float e0 = __expf(c[mi][n][0]);
                float e1 = __expf(c[mi][n][1]);
                float e2 = __expf(c[mi][n][2]);
                float e3 = __expf(c[mi][n][3]);
                lsum[2 * mi]     += e0 + e1;
                lsum[2 * mi + 1] += e2 + e3;
                psw[wb + lr * PADP + n * 8 + 2 * qd]         = f2tf32(e0);
                psw[wb + lr * PADP + n * 8 + 2 * qd + 1]     = f2tf32(e1);
                psw[wb + (lr + 8) * PADP + n * 8 + 2 * qd]     = f2tf32(e2);
                psw[wb + (lr + 8) * PADP + n * 8 + 2 * qd + 1] = f2tf32(e3);
            }
        }
        __syncwarp();

        // PV: o += e(32xk32) * V(k32 x 64)
        const uint32_t* vsu = (const uint32_t*)vs;
        #pragma unroll
        for (int kk2 = 0; kk2 < 4; kk2++) {
            uint32_t a[2][4];
            #pragma unroll
            for (int mi = 0; mi < 2; mi++) {
                int lr = mi * 16 + g;
                a[mi][0] = psw[wb + lr * PADP + kk2 * 8 + qd];
                a[mi][1] = psw[wb + (lr + 8) * PADP + kk2 * 8 + qd];
                a[mi][2] = psw[wb + lr * PADP + kk2 * 8 + qd + 4];
                a[mi][3] = psw[wb + (lr + 8) * PADP + kk2 * 8 + qd + 4];
            }
            int vr = wc * 32 + kk2 * 8 + qd;
            #pragma unroll
            for (int n = 0; n < 8; n++) {
                uint32_t b0 = vsu[vr * PADV + n * 8 + g];
                uint32_t b1 = vsu[(vr + 4) * PADV + n * 8 + g];
                mma_tf32(o[0][n], a[0][0], a[0][1], a[0][2], a[0][3], b0, b1);
                mma_tf32(o[1][n], a[1][0], a[1][1], a[1][2], a[1][3], b0, b1);
            }
        }
    }

    // reduce l across quad, then across wc halves
    #pragma unroll
    for (int j = 0; j < 4; j++) {
        lsum[j] += __shfl_xor_sync(0xffffffffu, lsum[j], 1);
        lsum[j] += __shfl_xor_sync(0xffffffffu, lsum[j], 2);
    }
    if (qd == 0) {
        #pragma unroll
        for (int j = 0; j < 4; j++) {
            int row = rbase + (j >> 1) * 16 + (j & 1) * 8 + g;
            lpart[wc * 128 + row] = lsum[j];
        }
    }
    __syncthreads();
    if (tid < TQ) {
        float L = lpart[tid] + lpart[128 + tid];
        ls[tid] = __frcp_rn(L);
        g_lnl[(size_t)bh * SLEN + q0 + tid] = __logf(L);
    }
    __syncthreads();

    // combine O across wc halves, scale, store
    if (wc == 1) {
        #pragma unroll
        for (int mi = 0; mi < 2; mi++) {
            int row = rbase + mi * 16 + g;
            #pragma unroll
            for (int n = 0; n < 8; n++) {
                obuf[row * PAD + n * 8 + 2 * qd]     = o[mi][n][0];
                obuf[row * PAD + n * 8 + 2 * qd + 1] = o[mi][n][1];
                obuf[(row + 8) * PAD + n * 8 + 2 * qd]     = o[mi][n][2];
                obuf[(row + 8) * PAD + n * 8 + 2 * qd + 1] = o[mi][n][3];
            }
        }
    }
    __syncthreads();
    if (wc == 0) {
        #pragma unroll
        for (int mi = 0; mi < 2; mi++) {
            int row = rbase + mi * 16 + g;
            float inv0 = ls[row], inv1 = ls[row + 8];
            float* orow0 = og + (size_t)(q0 + row) * HD;
            float* orow1 = orow0 + (size_t)8 * HD;
            #pragma unroll
            for (int n = 0; n < 8; n++) {
                int col = n * 8 + 2 * qd;
                float x0 = (o[mi][n][0] + obuf[row * PAD + col]) * inv0;
                float x1 = (o[mi][n][1] + obuf[row * PAD + col + 1]) * inv0;
                float x2 = (o[mi][n][2] + obuf[(row + 8) * PAD + col]) * inv1;
                float x3 = (o[mi][n][3] + obuf[(row + 8) * PAD + col + 1]) * inv1;
                *(float2*)(orow0 + col) = make_float2(x0, x1);
                *(float2*)(orow1 + col) = make_float2(x2, x3);
            }
        }
    }
}

// ============ kernel 2: recompute S, write attn = exp(s - lnl) ============
// Q a-fragments hoisted into registers (invariant across k-tiles) -> half the LDS.
__global__ __launch_bounds__(NTHREADS, 2)
void sdpa_attn(const float* __restrict__ q, const float* __restrict__ k,
               float* __restrict__ attn)
{
    extern __shared__ float smem[];
    float* qs = smem + K2_QS;
    float* ks = smem + K2_KS;

    const int qt = blockIdx.x, bh = blockIdx.y;
    const int q0 = qt * TQ;
    const int tid = threadIdx.x;
    const int lane = tid & 31, warp = tid >> 5;
    const int g = lane >> 2, qd = lane & 3;
    const int wr = warp >> 1, wc = warp & 1;
    const int rbase = wr * 32;

    const float* qg = q + (size_t)bh * SLEN * HD;
    const float* kg = k + (size_t)bh * SLEN * HD;
    float* ag = attn + (size_t)bh * SLEN * SLEN;

    {
        const float4* qg4 = (const float4*)(qg + (size_t)q0 * HD);
        #pragma unroll
        for (int i = 0; i < 8; i++) {
            int vv = tid + i * NTHREADS;
            int r = vv >> 4, c4 = vv & 15;
            float4 t = qg4[vv];
            uint32_t* dst = (uint32_t*)&qs[r * PAD + c4 * 4];
            dst[0] = f2tf32(t.x * 0.125f);
            dst[1] = f2tf32(t.y * 0.125f);
            dst[2] = f2tf32(t.z * 0.125f);
            dst[3] = f2tf32(t.w * 0.125f);
        }
    }
    __syncthreads();

    // hoist Q a-fragments into registers (qs never re-read afterwards)
    uint32_t qa[2][8][4];
    {
        const uint32_t* qsu = (const uint32_t*)qs;
        #pragma unroll
        for (int kk = 0; kk < 8; kk++)
            #pragma unroll
            for (int mi = 0; mi < 2; mi++) {
                int r = rbase + mi * 16 + g;
                qa[mi][kk][0] = qsu[r * PAD + kk * 8 + qd];
                qa[mi][kk][1] = qsu[(r + 8) * PAD + kk * 8 + qd];
                qa[mi][kk][2] = qsu[r * PAD + kk * 8 + qd + 4];
                qa[mi][kk][3] = qsu[(r + 8) * PAD + kk * 8 + qd + 4];
            }
    }

    // per-thread row lnl (4 rows)
    float lnl[4];
    #pragma unroll
    for (int j = 0; j < 4; j++) {
        int row = rbase + (j >> 1) * 16 + (j & 1) * 8 + g;
        lnl[j] = g_lnl[(size_t)bh * SLEN + q0 + row];
    }

    for (int kt = 0; kt < SLEN / TKV; kt++) {
        // prefetch K tile before the barrier
        const float4* kg4 = (const float4*)(kg + (size_t)kt * TKV * HD);
        float4 kreg[4];
        #pragma unroll
        for (int i = 0; i < 4; i++)
            kreg[i] = kg4[tid + i * NTHREADS];
        __syncthreads();
        #pragma unroll
        for (int i = 0; i < 4; i++) {
            int vv = tid + i * NTHREADS;
            int r = vv >> 4, c4 = vv & 15;
            uint32_t* dst = (uint32_t*)&ks[r * PAD + c4 * 4];
            dst[0] = f2tf32(kreg[i].x); dst[1] = f2tf32(kreg[i].y);
            dst[2] = f2tf32(kreg[i].z); dst[3] = f2tf32(kreg[i].w);
        }
        __syncthreads();

        float c[2][4][4];
        #pragma unroll
        for (int mi = 0; mi < 2; mi++)
            #pragma unroll
            for (int n = 0; n < 4; n++)
                { c[mi][n][0]=0.f; c[mi][n][1]=0.f; c[mi][n][2]=0.f; c[mi][n][3]=0.f; }

        const uint32_t* ksu = (const uint32_t*)ks;
        #pragma unroll
        for (int kk = 0; kk < 8; kk++) {
            #pragma unroll
            for (int n = 0; n < 4; n++) {
                int cc = wc * 32 + n * 8 + g;
                uint32_t b0 = ksu[cc * PAD + kk * 8 + qd];
                uint32_t b1 = ksu[cc * PAD + kk * 8 + qd + 4];
                mma_tf32(c[0][n], qa[0][kk][0], qa[0][kk][1], qa[0][kk][2], qa[0][kk][3], b0, b1);
                mma_tf32(c[1][n], qa[1][kk][0], qa[1][kk][1], qa[1][kk][2], qa[1][kk][3], b0, b1);
            }
        }

        // attn = exp(s - lnl), streaming store
        #pragma unroll
        for (int mi = 0; mi < 2; mi++) {
            int row = rbase + mi * 16 + g;
            float* ar0 = ag + (size_t)(q0 + row) * SLEN + kt * TKV + wc * 32;
            float* ar1 = ar0 + (size_t)8 * SLEN;
            float l0 = lnl[2 * mi], l1 = lnl[2 * mi + 1];
            #pragma unroll
            for (int n = 0; n < 4; n++) {
                int col = n * 8 + 2 * qd;
                float p0 = __expf(c[mi][n][0] - l0);
                float p1 = __expf(c[mi][n][1] - l0);
                float p2 = __expf(c[mi][n][2] - l1);
                float p3 = __expf(c[mi][n][3] - l1);
                *(float2*)(ar0 + col) = make_float2(p0, p1);
                *(float2*)(ar1 + col) = make_float2(p2, p3);
            }
        }
    }
}

extern "C" void kernel_launch(void* const* d_in, const int* in_sizes, int n_in,
                              void* d_out, int out_size)
{
    const float* q = (const float*)d_in[0];
    const float* k = (const float*)d_in[1];
    const float* v = (const float*)d_in[2];
    float* out  = (float*)d_out;
    float* attn = out + (size_t)NBH * SLEN * HD;

    cudaFuncSetAttribute(sdpa_flash, cudaFuncAttributeMaxDynamicSharedMemorySize, K1_SMEM_BYTES);
    cudaFuncSetAttribute(sdpa_attn,  cudaFuncAttributeMaxDynamicSharedMemorySize, K2_SMEM_BYTES);

    dim3 grid(SLEN / TQ, NBH);
    sdpa_flash<<<grid, NTHREADS, K1_SMEM_BYTES>>>(q, k, v, out);
    sdpa_attn<<<grid, NTHREADS, K2_SMEM_BYTES>>>(q, k, attn);
}